// round 1
// baseline (speedup 1.0000x reference)
#include <cuda_runtime.h>
#include <math.h>

#define B_   2
#define S_   4096
#define DM_  1024
#define H_   16
#define HD_  64
#define MROWS (B_ * S_)

// Scratch (device globals: no allocation allowed in kernel_launch)
__device__ float g_q[MROWS * DM_];
__device__ float g_k[MROWS * DM_];
__device__ float g_v[MROWS * DM_];
__device__ float g_attn[MROWS * DM_];

// ---------------------------------------------------------------------------
// GEMM: C[M,N] = X[M,K] @ W[K,N] + bias   (M=8192, N=K=1024)
// Tile 128x64x16, 256 threads, per-thread 8x4 register tile.
// ---------------------------------------------------------------------------
__global__ __launch_bounds__(256) void gemm_bias_kernel(
    const float* __restrict__ X, const float* __restrict__ W,
    const float* __restrict__ bias, float* __restrict__ C) {
  const int K = DM_, N = DM_;
  __shared__ float As[16][129];   // [k][m], padded to avoid STS conflicts
  __shared__ float Bs[16][64];    // [k][n]

  const int tid = threadIdx.x;
  const int m0 = blockIdx.y * 128;
  const int n0 = blockIdx.x * 64;

  const int tr = (tid >> 4) * 8;      // 16 row-groups of 8
  const int tc = (tid & 15) * 4;      // 16 col-groups of 4

  const int arow = tid >> 2;          // 0..63
  const int acol = (tid & 3) * 4;     // 0,4,8,12
  const int bk   = tid >> 4;          // 0..15
  const int bn   = (tid & 15) * 4;    // 0..60

  float acc[8][4];
#pragma unroll
  for (int i = 0; i < 8; i++)
#pragma unroll
    for (int j = 0; j < 4; j++) acc[i][j] = 0.f;

  for (int k0 = 0; k0 < K; k0 += 16) {
    // Load A tile (128x16) transposed into As[k][m]
#pragma unroll
    for (int rep = 0; rep < 2; rep++) {
      int r = rep * 64 + arow;
      float4 a = *(const float4*)(X + (long)(m0 + r) * K + k0 + acol);
      As[acol + 0][r] = a.x;
      As[acol + 1][r] = a.y;
      As[acol + 2][r] = a.z;
      As[acol + 3][r] = a.w;
    }
    // Load B tile (16x64)
    *(float4*)(&Bs[bk][bn]) =
        *(const float4*)(W + (long)(k0 + bk) * N + n0 + bn);
    __syncthreads();

#pragma unroll
    for (int k = 0; k < 16; k++) {
      float a[8];
#pragma unroll
      for (int i = 0; i < 8; i++) a[i] = As[k][tr + i];
      float4 b4 = *(float4*)(&Bs[k][tc]);
      float b[4] = {b4.x, b4.y, b4.z, b4.w};
#pragma unroll
      for (int i = 0; i < 8; i++)
#pragma unroll
        for (int j = 0; j < 4; j++)
          acc[i][j] = fmaf(a[i], b[j], acc[i][j]);
    }
    __syncthreads();
  }

  float4 bb = *(const float4*)(bias + n0 + tc);
#pragma unroll
  for (int i = 0; i < 8; i++) {
    float4 o;
    o.x = acc[i][0] + bb.x;
    o.y = acc[i][1] + bb.y;
    o.z = acc[i][2] + bb.z;
    o.w = acc[i][3] + bb.w;
    *(float4*)(C + (long)(m0 + tr + i) * N + n0 + tc) = o;
  }
}

// ---------------------------------------------------------------------------
// Flash attention, fp32.
// Grid: (S/64, B*H). Block: 256 threads (8 warps). Each warp owns 8 query
// rows. KV blocks of 64. Q and P packed float4-per-4-rows so each smem read
// feeds 16 FMAs (keeps kernel FMA-bound, not smem-bound).
//
// Dynamic smem layout (floats):
//   Qp  [64 d][64 rows]         4096   (Qp[d*64 + row], read as float4 groups)
//   KsT [64 d][66]              4224   (KsT[d*66 + kj], stride 66 for align)
//   Vs  [64 kj][64 d]           4096
//   Psw [8 warps][64 kj][8 r]   4096
// ---------------------------------------------------------------------------
__global__ __launch_bounds__(256) void flash_kernel(
    const float* __restrict__ Qg, const float* __restrict__ Kg,
    const float* __restrict__ Vg, float* __restrict__ Og) {
  extern __shared__ float sm[];
  float* Qp  = sm;              // 4096
  float* KsT = sm + 4096;       // 4224
  float* Vs  = sm + 8320;       // 4096
  float* Psw = sm + 12416;      // 4096

  const int tid  = threadIdx.x;
  const int warp = tid >> 5;
  const int L    = tid & 31;
  const int bh   = blockIdx.y;
  const int b    = bh >> 4;     // / H_
  const int h    = bh & 15;
  const int q0   = blockIdx.x * 64;
  const float scale = 0.125f;   // 1/sqrt(64)

  const long headoff = (long)h * HD_;
  const float* Qb    = Qg + (long)(b * S_) * DM_ + headoff;
  const float* Kbase = Kg + (long)(b * S_) * DM_ + headoff;
  const float* Vbase = Vg + (long)(b * S_) * DM_ + headoff;
  float* Ob          = Og + (long)(b * S_) * DM_ + headoff;

  // Load Q tile transposed into Qp[d*64 + row]
#pragma unroll
  for (int it = 0; it < 4; it++) {
    int idx = tid + it * 256;
    int row = idx >> 4;
    int d4  = (idx & 15) << 2;
    float4 qv = *(const float4*)(Qb + (long)(q0 + row) * DM_ + d4);
    Qp[(d4 + 0) * 64 + row] = qv.x;
    Qp[(d4 + 1) * 64 + row] = qv.y;
    Qp[(d4 + 2) * 64 + row] = qv.z;
    Qp[(d4 + 3) * 64 + row] = qv.w;
  }

  float m_r[8], l_r[8], o0[8], o1[8];
#pragma unroll
  for (int r = 0; r < 8; r++) {
    m_r[r] = -INFINITY;
    l_r[r] = 0.f;
    o0[r]  = 0.f;
    o1[r]  = 0.f;
  }

  float* PswW = Psw + warp * 512;
  const int g0base = warp * 8;  // float offset of this warp's 8 rows in Qp rows

  for (int kb = 0; kb < S_ / 64; kb++) {
    __syncthreads();
    const float* Kb = Kbase + (long)(kb * 64) * DM_;
    const float* Vb = Vbase + (long)(kb * 64) * DM_;
#pragma unroll
    for (int it = 0; it < 4; it++) {
      int idx = tid + it * 256;
      int row = idx >> 4;
      int d4  = (idx & 15) << 2;
      float4 kv = *(const float4*)(Kb + (long)row * DM_ + d4);
      KsT[(d4 + 0) * 66 + row] = kv.x;
      KsT[(d4 + 1) * 66 + row] = kv.y;
      KsT[(d4 + 2) * 66 + row] = kv.z;
      KsT[(d4 + 3) * 66 + row] = kv.w;
      float4 vv = *(const float4*)(Vb + (long)row * DM_ + d4);
      *(float4*)(Vs + row * 64 + d4) = vv;
    }
    __syncthreads();

    // ---- S = Q K^T : lane L owns kv columns 2L and 2L+1 ----
    float s0[8], s1[8];
#pragma unroll
    for (int r = 0; r < 8; r++) { s0[r] = 0.f; s1[r] = 0.f; }
#pragma unroll 4
    for (int d = 0; d < 64; d++) {
      float2 kk = *(float2*)(KsT + d * 66 + 2 * L);
      float4 qa = *(float4*)(Qp + d * 64 + g0base);
      float4 qb = *(float4*)(Qp + d * 64 + g0base + 4);
      float qav[4] = {qa.x, qa.y, qa.z, qa.w};
      float qbv[4] = {qb.x, qb.y, qb.z, qb.w};
#pragma unroll
      for (int r = 0; r < 4; r++) {
        s0[r]     = fmaf(qav[r], kk.x, s0[r]);
        s1[r]     = fmaf(qav[r], kk.y, s1[r]);
        s0[r + 4] = fmaf(qbv[r], kk.x, s0[r + 4]);
        s1[r + 4] = fmaf(qbv[r], kk.y, s1[r + 4]);
      }
    }

    // ---- online softmax per row ----
    float p0[8], p1[8];
#pragma unroll
    for (int r = 0; r < 8; r++) {
      float a0 = s0[r] * scale;
      float a1 = s1[r] * scale;
      float mx = fmaxf(a0, a1);
#pragma unroll
      for (int off = 16; off > 0; off >>= 1)
        mx = fmaxf(mx, __shfl_xor_sync(0xffffffffu, mx, off));
      float mnew  = fmaxf(m_r[r], mx);
      float e0    = __expf(a0 - mnew);
      float e1    = __expf(a1 - mnew);
      float alpha = __expf(m_r[r] - mnew);
      m_r[r] = mnew;
      float ps = e0 + e1;
#pragma unroll
      for (int off = 16; off > 0; off >>= 1)
        ps += __shfl_xor_sync(0xffffffffu, ps, off);
      l_r[r] = l_r[r] * alpha + ps;
      o0[r] *= alpha;
      o1[r] *= alpha;
      p0[r] = e0;
      p1[r] = e1;
    }

    // pack P: Psw[kj*8 + r] (float4 per 4 rows)
    *(float4*)(PswW + (2 * L) * 8)         = make_float4(p0[0], p0[1], p0[2], p0[3]);
    *(float4*)(PswW + (2 * L) * 8 + 4)     = make_float4(p0[4], p0[5], p0[6], p0[7]);
    *(float4*)(PswW + (2 * L + 1) * 8)     = make_float4(p1[0], p1[1], p1[2], p1[3]);
    *(float4*)(PswW + (2 * L + 1) * 8 + 4) = make_float4(p1[4], p1[5], p1[6], p1[7]);
    __syncwarp();

    // ---- O += P V : lane L owns head dims 2L and 2L+1 ----
#pragma unroll 4
    for (int kj = 0; kj < 64; kj++) {
      float4 pa = *(float4*)(PswW + kj * 8);
      float4 pb = *(float4*)(PswW + kj * 8 + 4);
      float2 vv = *(float2*)(Vs + kj * 64 + 2 * L);
      float pav[4] = {pa.x, pa.y, pa.z, pa.w};
      float pbv[4] = {pb.x, pb.y, pb.z, pb.w};
#pragma unroll
      for (int r = 0; r < 4; r++) {
        o0[r]     = fmaf(pav[r], vv.x, o0[r]);
        o1[r]     = fmaf(pav[r], vv.y, o1[r]);
        o0[r + 4] = fmaf(pbv[r], vv.x, o0[r + 4]);
        o1[r + 4] = fmaf(pbv[r], vv.y, o1[r + 4]);
      }
    }
    __syncwarp();
  }

  // epilogue: normalize and store
#pragma unroll
  for (int r = 0; r < 8; r++) {
    int row   = warp * 8 + r;
    float inv = 1.f / l_r[r];
    float2 o  = make_float2(o0[r] * inv, o1[r] * inv);
    *(float2*)(Ob + (long)(q0 + row) * DM_ + 2 * L) = o;
  }
}

// ---------------------------------------------------------------------------
extern "C" void kernel_launch(void* const* d_in, const int* in_sizes, int n_in,
                              void* d_out, int out_size) {
  const float* x  = (const float*)d_in[0];
  const float* Wq = (const float*)d_in[1];
  const float* bq = (const float*)d_in[2];
  const float* Wk = (const float*)d_in[3];
  const float* bk = (const float*)d_in[4];
  const float* Wv = (const float*)d_in[5];
  const float* bv = (const float*)d_in[6];
  const float* Wo = (const float*)d_in[7];
  const float* bo = (const float*)d_in[8];
  float* out = (float*)d_out;

  float *q, *k, *v, *attn;
  cudaGetSymbolAddress((void**)&q, g_q);
  cudaGetSymbolAddress((void**)&k, g_k);
  cudaGetSymbolAddress((void**)&v, g_v);
  cudaGetSymbolAddress((void**)&attn, g_attn);

  dim3 ggrid(DM_ / 64, MROWS / 128);
  gemm_bias_kernel<<<ggrid, 256>>>(x, Wq, bq, q);
  gemm_bias_kernel<<<ggrid, 256>>>(x, Wk, bk, k);
  gemm_bias_kernel<<<ggrid, 256>>>(x, Wv, bv, v);

  const int flash_smem = 16512 * (int)sizeof(float);  // 66048 B
  cudaFuncSetAttribute(flash_kernel,
                       cudaFuncAttributeMaxDynamicSharedMemorySize, flash_smem);
  flash_kernel<<<dim3(S_ / 64, B_ * H_), 256, flash_smem>>>(q, k, v, attn);

  gemm_bias_kernel<<<ggrid, 256>>>(attn, Wo, bo, out);
}

// round 2
// speedup vs baseline: 5.2842x; 5.2842x over previous
#include <cuda_runtime.h>
#include <math.h>

#define B_   2
#define S_   4096
#define DM_  1024
#define H_   16
#define HD_  64
#define MROWS (B_ * S_)

__device__ float g_q[MROWS * DM_];
__device__ float g_k[MROWS * DM_];
__device__ float g_v[MROWS * DM_];
__device__ float g_attn[MROWS * DM_];

__device__ __forceinline__ unsigned f2tf(float x) {
  unsigned r;
  asm("cvt.rna.tf32.f32 %0, %1;" : "=r"(r) : "f"(x));
  return r;
}

__device__ __forceinline__ void mma_tf32(float c[4], const unsigned a[4],
                                         const unsigned b[2]) {
  asm volatile(
      "mma.sync.aligned.m16n8k8.row.col.f32.tf32.tf32.f32 "
      "{%0,%1,%2,%3}, {%4,%5,%6,%7}, {%8,%9}, {%0,%1,%2,%3};"
      : "+f"(c[0]), "+f"(c[1]), "+f"(c[2]), "+f"(c[3])
      : "r"(a[0]), "r"(a[1]), "r"(a[2]), "r"(a[3]), "r"(b[0]), "r"(b[1]));
}

// ---------------------------------------------------------------------------
// GEMM: C[M,N] = X[M,K] @ W[K,N] + bias  via tf32 mma.sync
// Block tile 128x128x32. 8 warps: wm in 0..3 (32 rows), wn in 0..1 (64 cols).
// ---------------------------------------------------------------------------
__global__ __launch_bounds__(256) void gemm_mma_kernel(
    const float* __restrict__ X, const float* __restrict__ W,
    const float* __restrict__ bias, float* __restrict__ C) {
  __shared__ unsigned As[128 * 36];  // [row][k] pad 36 -> conflict-free frags
  __shared__ unsigned Bs[32 * 136];  // [k][n]   pad 136

  const int tid  = threadIdx.x;
  const int lane = tid & 31;
  const int wid  = tid >> 5;
  const int g    = lane >> 2;   // groupID
  const int tg   = lane & 3;    // thread-in-group
  const int wm   = wid & 3;
  const int wn   = wid >> 2;
  const long m0  = (long)blockIdx.y * 128;
  const int  n0  = blockIdx.x * 128;

  float4 ra[4], rb[4];
#pragma unroll
  for (int i = 0; i < 4; i++) {
    int idx = tid + i * 256;
    ra[i] = *(const float4*)(X + (m0 + (idx >> 3)) * DM_ + ((idx & 7) << 2));
    rb[i] = *(const float4*)(W + (long)(idx >> 5) * DM_ + n0 + ((idx & 31) << 2));
  }

  float acc[2][8][4];
#pragma unroll
  for (int mt = 0; mt < 2; mt++)
#pragma unroll
    for (int nt = 0; nt < 8; nt++)
#pragma unroll
      for (int j = 0; j < 4; j++) acc[mt][nt][j] = 0.f;

  for (int k0 = 0; k0 < DM_; k0 += 32) {
    __syncthreads();
#pragma unroll
    for (int i = 0; i < 4; i++) {
      int idx = tid + i * 256;
      int r = idx >> 3, k4 = (idx & 7) << 2;
      As[r * 36 + k4 + 0] = f2tf(ra[i].x);
      As[r * 36 + k4 + 1] = f2tf(ra[i].y);
      As[r * 36 + k4 + 2] = f2tf(ra[i].z);
      As[r * 36 + k4 + 3] = f2tf(ra[i].w);
      int bk = idx >> 5, bn = (idx & 31) << 2;
      Bs[bk * 136 + bn + 0] = f2tf(rb[i].x);
      Bs[bk * 136 + bn + 1] = f2tf(rb[i].y);
      Bs[bk * 136 + bn + 2] = f2tf(rb[i].z);
      Bs[bk * 136 + bn + 3] = f2tf(rb[i].w);
    }
    __syncthreads();

    if (k0 + 32 < DM_) {
#pragma unroll
      for (int i = 0; i < 4; i++) {
        int idx = tid + i * 256;
        ra[i] = *(const float4*)(X + (m0 + (idx >> 3)) * DM_ + k0 + 32 +
                                 ((idx & 7) << 2));
        rb[i] = *(const float4*)(W + (long)(k0 + 32 + (idx >> 5)) * DM_ + n0 +
                                 ((idx & 31) << 2));
      }
    }

#pragma unroll
    for (int ks = 0; ks < 4; ks++) {
      unsigned a[2][4];
#pragma unroll
      for (int mt = 0; mt < 2; mt++) {
        int row = wm * 32 + mt * 16 + g;
        int col = ks * 8 + tg;
        a[mt][0] = As[row * 36 + col];
        a[mt][1] = As[(row + 8) * 36 + col];
        a[mt][2] = As[row * 36 + col + 4];
        a[mt][3] = As[(row + 8) * 36 + col + 4];
      }
#pragma unroll
      for (int nt = 0; nt < 8; nt++) {
        unsigned b[2];
        int n  = wn * 64 + nt * 8 + g;
        int kk = ks * 8 + tg;
        b[0] = Bs[kk * 136 + n];
        b[1] = Bs[(kk + 4) * 136 + n];
        mma_tf32(acc[0][nt], a[0], b);
        mma_tf32(acc[1][nt], a[1], b);
      }
    }
  }

#pragma unroll
  for (int mt = 0; mt < 2; mt++) {
    long row = m0 + wm * 32 + mt * 16 + g;
#pragma unroll
    for (int nt = 0; nt < 8; nt++) {
      int col = n0 + wn * 64 + nt * 8 + 2 * tg;
      float2 bb = *(const float2*)(bias + col);
      float2 o0 = make_float2(acc[mt][nt][0] + bb.x, acc[mt][nt][1] + bb.y);
      float2 o1 = make_float2(acc[mt][nt][2] + bb.x, acc[mt][nt][3] + bb.y);
      *(float2*)(C + row * DM_ + col)       = o0;
      *(float2*)(C + (row + 8) * DM_ + col) = o1;
    }
  }
}

// ---------------------------------------------------------------------------
// Flash attention with tf32 mma. CTA: 128 q rows, 8 warps x 16 rows.
// KV blocks of 64. Q A-fragments live in registers for the whole KV loop.
// Smem (unsigned/tf32): Ks[64][68], Vs[64][72], Ps[128][68]  = 70656 B
// ---------------------------------------------------------------------------
__global__ __launch_bounds__(256) void flash_tc_kernel(
    const float* __restrict__ Qg, const float* __restrict__ Kg,
    const float* __restrict__ Vg, float* __restrict__ Og) {
  extern __shared__ unsigned sm[];
  unsigned* Ks = sm;                       // 64*68
  unsigned* Vs = sm + 64 * 68;             // 64*72
  unsigned* Ps = sm + 64 * 68 + 64 * 72;   // 128*68

  const int tid  = threadIdx.x;
  const int lane = tid & 31;
  const int wid  = tid >> 5;
  const int g    = lane >> 2;
  const int tg   = lane & 3;
  const int bh   = blockIdx.y;
  const int b    = bh >> 4;
  const int h    = bh & 15;
  const int q0   = blockIdx.x * 128;

  const float* Qb  = Qg + ((long)(b * S_ + q0)) * DM_ + h * HD_;
  const float* Kb0 = Kg + ((long)b * S_) * DM_ + h * HD_;
  const float* Vb0 = Vg + ((long)b * S_) * DM_ + h * HD_;
  float* Ob        = Og + ((long)(b * S_ + q0)) * DM_ + h * HD_;

  // Q A-frags (pre-scaled by 1/sqrt(64) = 0.125, exact)
  unsigned qa[8][4];
  {
    int qrow = wid * 16 + g;
#pragma unroll
    for (int ks = 0; ks < 8; ks++) {
      int c = ks * 8 + tg;
      qa[ks][0] = f2tf(0.125f * Qb[(long)qrow * DM_ + c]);
      qa[ks][1] = f2tf(0.125f * Qb[(long)(qrow + 8) * DM_ + c]);
      qa[ks][2] = f2tf(0.125f * Qb[(long)qrow * DM_ + c + 4]);
      qa[ks][3] = f2tf(0.125f * Qb[(long)(qrow + 8) * DM_ + c + 4]);
    }
  }

  float oacc[8][4];
#pragma unroll
  for (int nt = 0; nt < 8; nt++)
#pragma unroll
    for (int j = 0; j < 4; j++) oacc[nt][j] = 0.f;
  float m0r = -INFINITY, m1r = -INFINITY, l0 = 0.f, l1 = 0.f;

  float4 kreg[4], vreg[4];
#pragma unroll
  for (int i = 0; i < 4; i++) {
    int idx = tid + i * 256;
    int kv = idx >> 4, d4 = (idx & 15) << 2;
    kreg[i] = *(const float4*)(Kb0 + (long)kv * DM_ + d4);
    vreg[i] = *(const float4*)(Vb0 + (long)kv * DM_ + d4);
  }

  for (int kb = 0; kb < S_ / 64; kb++) {
    __syncthreads();
#pragma unroll
    for (int i = 0; i < 4; i++) {
      int idx = tid + i * 256;
      int kv = idx >> 4, d4 = (idx & 15) << 2;
      Ks[kv * 68 + d4 + 0] = f2tf(kreg[i].x);
      Ks[kv * 68 + d4 + 1] = f2tf(kreg[i].y);
      Ks[kv * 68 + d4 + 2] = f2tf(kreg[i].z);
      Ks[kv * 68 + d4 + 3] = f2tf(kreg[i].w);
      Vs[kv * 72 + d4 + 0] = f2tf(vreg[i].x);
      Vs[kv * 72 + d4 + 1] = f2tf(vreg[i].y);
      Vs[kv * 72 + d4 + 2] = f2tf(vreg[i].z);
      Vs[kv * 72 + d4 + 3] = f2tf(vreg[i].w);
    }
    __syncthreads();

    if (kb + 1 < S_ / 64) {
      const float* Kb = Kb0 + (long)((kb + 1) * 64) * DM_;
      const float* Vb = Vb0 + (long)((kb + 1) * 64) * DM_;
#pragma unroll
      for (int i = 0; i < 4; i++) {
        int idx = tid + i * 256;
        int kv = idx >> 4, d4 = (idx & 15) << 2;
        kreg[i] = *(const float4*)(Kb + (long)kv * DM_ + d4);
        vreg[i] = *(const float4*)(Vb + (long)kv * DM_ + d4);
      }
    }

    // ---- S = Q K^T ----
    float sacc[8][4];
#pragma unroll
    for (int nt = 0; nt < 8; nt++)
#pragma unroll
      for (int j = 0; j < 4; j++) sacc[nt][j] = 0.f;
#pragma unroll
    for (int nt = 0; nt < 8; nt++) {
#pragma unroll
      for (int ks = 0; ks < 8; ks++) {
        unsigned bf[2];
        int n  = nt * 8 + g;    // kv index
        int kk = ks * 8 + tg;   // d index
        bf[0] = Ks[n * 68 + kk];
        bf[1] = Ks[n * 68 + kk + 4];
        mma_tf32(sacc[nt], qa[ks], bf);
      }
    }

    // ---- online softmax (rows g and g+8 of this warp's 16) ----
    float mx0 = -INFINITY, mx1 = -INFINITY;
#pragma unroll
    for (int nt = 0; nt < 8; nt++) {
      mx0 = fmaxf(mx0, fmaxf(sacc[nt][0], sacc[nt][1]));
      mx1 = fmaxf(mx1, fmaxf(sacc[nt][2], sacc[nt][3]));
    }
#pragma unroll
    for (int off = 1; off <= 2; off <<= 1) {
      mx0 = fmaxf(mx0, __shfl_xor_sync(0xffffffffu, mx0, off));
      mx1 = fmaxf(mx1, __shfl_xor_sync(0xffffffffu, mx1, off));
    }
    float mn0 = fmaxf(m0r, mx0), mn1 = fmaxf(m1r, mx1);
    float al0 = __expf(m0r - mn0), al1 = __expf(m1r - mn1);
    m0r = mn0; m1r = mn1;

    float ps0 = 0.f, ps1 = 0.f;
#pragma unroll
    for (int nt = 0; nt < 8; nt++) {
      sacc[nt][0] = __expf(sacc[nt][0] - mn0);
      sacc[nt][1] = __expf(sacc[nt][1] - mn0);
      sacc[nt][2] = __expf(sacc[nt][2] - mn1);
      sacc[nt][3] = __expf(sacc[nt][3] - mn1);
      ps0 += sacc[nt][0] + sacc[nt][1];
      ps1 += sacc[nt][2] + sacc[nt][3];
    }
#pragma unroll
    for (int off = 1; off <= 2; off <<= 1) {
      ps0 += __shfl_xor_sync(0xffffffffu, ps0, off);
      ps1 += __shfl_xor_sync(0xffffffffu, ps1, off);
    }
    l0 = l0 * al0 + ps0;
    l1 = l1 * al1 + ps1;
#pragma unroll
    for (int nt = 0; nt < 8; nt++) {
      oacc[nt][0] *= al0;
      oacc[nt][1] *= al0;
      oacc[nt][2] *= al1;
      oacc[nt][3] *= al1;
    }

    // ---- store P (tf32) ----
    {
      int pr = wid * 16 + g;
#pragma unroll
      for (int nt = 0; nt < 8; nt++) {
        int col = nt * 8 + 2 * tg;
        Ps[pr * 68 + col]           = f2tf(sacc[nt][0]);
        Ps[pr * 68 + col + 1]       = f2tf(sacc[nt][1]);
        Ps[(pr + 8) * 68 + col]     = f2tf(sacc[nt][2]);
        Ps[(pr + 8) * 68 + col + 1] = f2tf(sacc[nt][3]);
      }
    }
    __syncwarp();

    // ---- O += P V ----
#pragma unroll
    for (int ks = 0; ks < 8; ks++) {
      unsigned pa[4];
      int pr  = wid * 16 + g;
      int col = ks * 8 + tg;
      pa[0] = Ps[pr * 68 + col];
      pa[1] = Ps[(pr + 8) * 68 + col];
      pa[2] = Ps[pr * 68 + col + 4];
      pa[3] = Ps[(pr + 8) * 68 + col + 4];
#pragma unroll
      for (int nt = 0; nt < 8; nt++) {
        unsigned bf[2];
        int n  = nt * 8 + g;    // d index
        int kk = ks * 8 + tg;   // kv index
        bf[0] = Vs[kk * 72 + n];
        bf[1] = Vs[(kk + 4) * 72 + n];
        mma_tf32(oacc[nt], pa, bf);
      }
    }
  }

  // epilogue
  float inv0 = 1.f / l0, inv1 = 1.f / l1;
  int row = wid * 16 + g;
#pragma unroll
  for (int nt = 0; nt < 8; nt++) {
    int col = nt * 8 + 2 * tg;
    float2 o0 = make_float2(oacc[nt][0] * inv0, oacc[nt][1] * inv0);
    float2 o1 = make_float2(oacc[nt][2] * inv1, oacc[nt][3] * inv1);
    *(float2*)(Ob + (long)row * DM_ + col)       = o0;
    *(float2*)(Ob + (long)(row + 8) * DM_ + col) = o1;
  }
}

// ---------------------------------------------------------------------------
extern "C" void kernel_launch(void* const* d_in, const int* in_sizes, int n_in,
                              void* d_out, int out_size) {
  const float* x  = (const float*)d_in[0];
  const float* Wq = (const float*)d_in[1];
  const float* bq = (const float*)d_in[2];
  const float* Wk = (const float*)d_in[3];
  const float* bk = (const float*)d_in[4];
  const float* Wv = (const float*)d_in[5];
  const float* bv = (const float*)d_in[6];
  const float* Wo = (const float*)d_in[7];
  const float* bo = (const float*)d_in[8];
  float* out = (float*)d_out;

  float *q, *k, *v, *attn;
  cudaGetSymbolAddress((void**)&q, g_q);
  cudaGetSymbolAddress((void**)&k, g_k);
  cudaGetSymbolAddress((void**)&v, g_v);
  cudaGetSymbolAddress((void**)&attn, g_attn);

  dim3 ggrid(DM_ / 128, MROWS / 128);
  gemm_mma_kernel<<<ggrid, 256>>>(x, Wq, bq, q);
  gemm_mma_kernel<<<ggrid, 256>>>(x, Wk, bk, k);
  gemm_mma_kernel<<<ggrid, 256>>>(x, Wv, bv, v);

  const int flash_smem = (64 * 68 + 64 * 72 + 128 * 68) * (int)sizeof(unsigned);
  cudaFuncSetAttribute(flash_tc_kernel,
                       cudaFuncAttributeMaxDynamicSharedMemorySize, flash_smem);
  flash_tc_kernel<<<dim3(S_ / 128, B_ * H_), 256, flash_smem>>>(q, k, v, attn);

  gemm_mma_kernel<<<ggrid, 256>>>(attn, Wo, bo, out);
}